// round 12
// baseline (speedup 1.0000x reference)
#include <cuda_runtime.h>
#include <cuda_bf16.h>
#include <cuda_fp16.h>
#include <math.h>
#include <stdint.h>

// Problem constants
#define B_      128
#define S_      256
#define MW      21
#define VOCAB   100
#define ECHAR   50
#define EWORD   256
#define KW      5
#define T_OUT   17
#define NWORDS  (B_ * S_)       // 32768

// Scratch
__device__ float   g_P [VOCAB * KW * EWORD];
__device__ float   g_Y [NWORDS * EWORD];      // fp32 (exact passthrough)
__device__ __half  g_Yf[NWORDS * EWORD];      // fp16 Y (GEMM A operand)
// Interleaved weights: row r = 2*n + pg (pg: 0=proj, 1=gate), [r][k], fp16
__device__ __half  g_Wf[512 * EWORD];

typedef unsigned long long ull;

__device__ __forceinline__ uint32_t smem_u32(const void* p) {
    uint32_t a;
    asm("{ .reg .u64 t; cvta.to.shared.u64 t, %1; cvt.u32.u64 %0, t; }"
        : "=r"(a) : "l"(p));
    return a;
}

// ---- warp-level mma + cp.async (sm_80 baseline PTX) ----
#define LDSM4(r, addr) \
    asm volatile("ldmatrix.sync.aligned.m8n8.x4.shared.b16 {%0,%1,%2,%3}, [%4];" \
        : "=r"((r)[0]), "=r"((r)[1]), "=r"((r)[2]), "=r"((r)[3]) : "r"(addr))

#define MMA_F16(d, a, b0, b1) \
    asm volatile("mma.sync.aligned.m16n8k16.row.col.f32.f16.f16.f32 " \
        "{%0,%1,%2,%3}, {%4,%5,%6,%7}, {%8,%9}, {%0,%1,%2,%3};" \
        : "+f"((d)[0]), "+f"((d)[1]), "+f"((d)[2]), "+f"((d)[3]) \
        : "r"((a)[0]), "r"((a)[1]), "r"((a)[2]), "r"((a)[3]), \
          "r"(b0), "r"(b1))

#define CP16(dst, src) \
    asm volatile("cp.async.cg.shared.global [%0], [%1], 16;" \
                 :: "r"(dst), "l"(src) : "memory")
#define CP_COMMIT() asm volatile("cp.async.commit_group;" ::: "memory")
#define CP_WAIT0()  asm volatile("cp.async.wait_group 0;" ::: "memory")

// ---------------------------------------------------------------------------
// Kernel 1: P[v,k,e] — 128 blocks x 2 e, staged in SMEM coalesced.
// ---------------------------------------------------------------------------
__global__ void __launch_bounds__(512)
precomputeP(const float* __restrict__ emb, const float* __restrict__ cw) {
    __shared__ float s_emb[VOCAB * ECHAR];
    __shared__ float s_cw[2 * ECHAR * KW];
    const int e0 = blockIdx.x * 2;
    const int tid = threadIdx.x;

    for (int i = tid; i < VOCAB * ECHAR; i += 512) s_emb[i] = emb[i];
    if (tid < 2 * ECHAR * KW)
        s_cw[tid] = cw[e0 * (ECHAR * KW) + tid];
    __syncthreads();

    for (int p = tid; p < VOCAB * KW * 2; p += 512) {
        const int v   = p / (KW * 2);
        const int rem = p - v * (KW * 2);
        const int k   = rem >> 1;
        const int ei  = rem & 1;
        float a = 0.f;
#pragma unroll 10
        for (int c = 0; c < ECHAR; c++)
            a += s_cw[ei * (ECHAR * KW) + c * KW + k] * s_emb[v * ECHAR + c];
        g_P[v * (KW * EWORD) + k * EWORD + e0 + ei] = a;
    }
}

// ---------------------------------------------------------------------------
// Kernel 2: conv-as-table-lookup + ReLU + maxpool — fully fp16 inner loop.
// grid (128, 5): y<4 conv slices; y==4 W fp16 convert plane.
// ---------------------------------------------------------------------------
#define SY_STRIDE 257

__global__ void __launch_bounds__(512)
conv_max_kernel(const int* __restrict__ ps, const float* __restrict__ cb,
                const float* __restrict__ Wp, const float* __restrict__ Wg) {
    const int tid = threadIdx.x;

    if (blockIdx.y == 4) {
        const int idx = blockIdx.x * 512 + tid;
        const int n = idx >> 8, k = idx & 255;
        g_Wf[(2 * n + 0) * EWORD + k] = __float2half_rn(Wp[idx]);
        g_Wf[(2 * n + 1) * EWORD + k] = __float2half_rn(Wg[idx]);
        return;
    }

    extern __shared__ char smraw[];
    __half2* sPh = (__half2*)smraw;
    float*   sY  = (float*)(smraw + VOCAB * KW * 32 * 4);

    const int e0 = blockIdx.y * 64;
    const int w0 = blockIdx.x * 256;

    for (int i = tid; i < VOCAB * KW * 32; i += 512) {
        const int v  = i / 160;
        const int r  = i - v * 160;
        const int k  = r >> 5;
        const int ep = r & 31;
        const float2 f = *(const float2*)&g_P[v * (KW * EWORD) + k * EWORD
                                              + e0 + ep * 2];
        sPh[i] = __float22half2_rn(f);
    }
    __syncthreads();

    const int el2 = tid & 31;
    const int wl  = tid >> 5;
    const float2 bias = *(const float2*)&cb[e0 + el2 * 2];

    for (int it = 0; it < 16; it++) {
        const int wloc = it * 16 + wl;
        const int* cid = ps + (w0 + wloc) * MW;

        int off[MW];
#pragma unroll
        for (int j = 0; j < MW; j++)
            off[j] = __ldg(&cid[j]) * (KW * 32) + el2;

        __half2 mh = __float2half2_rn(-60000.f);
#pragma unroll
        for (int t = 0; t < T_OUT; t++) {
            const __half2 u0 = sPh[off[t + 0] + 0 * 32];
            const __half2 u1 = sPh[off[t + 1] + 1 * 32];
            const __half2 u2 = sPh[off[t + 2] + 2 * 32];
            const __half2 u3 = sPh[off[t + 3] + 3 * 32];
            const __half2 u4 = sPh[off[t + 4] + 4 * 32];
            const __half2 s = __hadd2(__hadd2(__hadd2(u0, u1),
                                              __hadd2(u2, u3)), u4);
            mh = __hmax2(mh, s);
        }
        const float2 f = __half22float2(mh);
        sY[(el2 * 2 + 0) * SY_STRIDE + wloc] = fmaxf(f.x + bias.x, 0.f);
        sY[(el2 * 2 + 1) * SY_STRIDE + wloc] = fmaxf(f.y + bias.y, 0.f);
    }
    __syncthreads();

    for (int i = tid; i < 64 * 256; i += 512) {
        const int w = i >> 6, e = i & 63;
        const float y = sY[e * SY_STRIDE + w];
        const int gi = (w0 + w) * EWORD + e0 + e;
        g_Y[gi]  = y;
        g_Yf[gi] = __float2half_rn(y);
    }
}

// ---------------------------------------------------------------------------
// Kernel 3: highway dual-GEMM — chunk-free. Full K=256 staged once, then 16
// barrier-free ks iterations. CTA 256 thr (8 warps: wm2 x wn4), tile
// 128m x 64 interleaved rows (32 n). Warp tile 64m x 16 rows: acc 32 regs,
// deep ptxas pipelining. grid (256, 8), 2 CTAs/SM.
// ---------------------------------------------------------------------------
#define RSTR    528                     // 512B data + 16B pad (33*16, odd)
#define OFF_A   0                       // 128 * 528 = 67584
#define OFF_B   67584                   // 64 * 528  = 33792
#define SM3_B   101376
#define EPI_STR 36                      // epilogue smem stride (floats)

__global__ void __launch_bounds__(256, 2)
highway_mma(const float* __restrict__ bp, const float* __restrict__ bg,
            float* __restrict__ out) {
    extern __shared__ char sm[];
    const uint32_t smb = smem_u32(sm);

    const int tid = threadIdx.x;
    const int wid = tid >> 5;
    const int lane = tid & 31;
    const int wm = wid & 1;          // 64m each
    const int wn = wid >> 1;         // 16 interleaved rows each
    const int m0 = blockIdx.x * 128;
    const int rb = blockIdx.y * 64;  // interleaved-row base
    const int nb = rb >> 1;          // 32-wide n base

    // ---- prologue: stage full A (128x256) and B (64x256) fp16 tiles ----
#pragma unroll
    for (int q = 0; q < 16; q++) {           // A: 4096 16B-lines
        const int idx = tid + q * 256;
        const int r = idx >> 5, c = idx & 31;
        CP16(smb + OFF_A + r * RSTR + c * 16,
             (const char*)g_Yf + ((long)(m0 + r) * EWORD + c * 8) * 2);
    }
#pragma unroll
    for (int q = 0; q < 8; q++) {            // B: 2048 16B-lines
        const int idx = tid + q * 256;
        const int r = idx >> 5, c = idx & 31;
        CP16(smb + OFF_B + r * RSTR + c * 16,
             (const char*)g_Wf + ((long)(rb + r) * EWORD + c * 8) * 2);
    }
    CP_COMMIT();

    float acc[4][2][4];
#pragma unroll
    for (int i = 0; i < 4; i++)
#pragma unroll
        for (int j = 0; j < 2; j++)
#pragma unroll
            for (int c = 0; c < 4; c++) acc[i][j][c] = 0.f;

    const int laneRow = lane & 15;
    const int laneHi  = (lane >> 4) * 16;

    CP_WAIT0();
    __syncthreads();

    // ---- mainloop: 16 ks iterations, no barriers ----
#pragma unroll
    for (int ks = 0; ks < 16; ks++) {
        const uint32_t kboff = ks * 32 + laneHi;

        uint32_t af[4][4];
#pragma unroll
        for (int mt = 0; mt < 4; mt++)
            LDSM4(af[mt], smb + OFF_A
                  + (wm * 64 + mt * 16 + laneRow) * RSTR + kboff);

        uint32_t q[4];
        LDSM4(q, smb + OFF_B + (wn * 16 + laneRow) * RSTR + kboff);

#pragma unroll
        for (int mt = 0; mt < 4; mt++) {
            MMA_F16(acc[mt][0], af[mt], q[0], q[2]);
            MMA_F16(acc[mt][1], af[mt], q[1], q[3]);
        }
    }
    __syncthreads();

    // ---- Epilogue phase 1: (p, g) to conflict-free padded SMEM tiles ----
    float* sPf = (float*)sm;                  // [128][EPI_STR]
    float* sGf = sPf + 128 * EPI_STR;
    const int nl0 = wn * 8 + (lane & 3);

#pragma unroll
    for (int mt = 0; mt < 4; mt++) {
        const int ml = wm * 64 + mt * 16 + (lane >> 2);
#pragma unroll
        for (int j = 0; j < 2; j++) {
            const int nl = nl0 + j * 4;
            const float bpn = __ldg(&bp[nb + nl]);
            const float bgn = __ldg(&bg[nb + nl]);
            sPf[ml * EPI_STR + nl] = fmaxf(acc[mt][j][0] + bpn, 0.f);
            sGf[ml * EPI_STR + nl] =
                1.f / (1.f + __expf(-(acc[mt][j][1] + bgn)));
            sPf[(ml + 8) * EPI_STR + nl] = fmaxf(acc[mt][j][2] + bpn, 0.f);
            sGf[(ml + 8) * EPI_STR + nl] =
                1.f / (1.f + __expf(-(acc[mt][j][3] + bgn)));
        }
    }
    __syncthreads();

    // ---- Epilogue phase 2: fully coalesced float4 pass ----
#pragma unroll
    for (int qq = 0; qq < 4; qq++) {
        const int i  = tid + qq * 256;        // 0..1023
        const int ml = i >> 3;
        const int c4 = (i & 7) << 2;
        const int gi = (m0 + ml) * EWORD + nb + c4;
        const float4 y4 = *(const float4*)&g_Y[gi];
        const float4 p4 = *(const float4*)&sPf[ml * EPI_STR + c4];
        const float4 g4 = *(const float4*)&sGf[ml * EPI_STR + c4];
        float4 o;
        o.x = g4.x * p4.x + (1.f - g4.x) * y4.x;
        o.y = g4.y * p4.y + (1.f - g4.y) * y4.y;
        o.z = g4.z * p4.z + (1.f - g4.z) * y4.z;
        o.w = g4.w * p4.w + (1.f - g4.w) * y4.w;
        *(float4*)&out[gi] = o;
    }
}

// ---------------------------------------------------------------------------
extern "C" void kernel_launch(void* const* d_in, const int* in_sizes, int n_in,
                              void* d_out, int out_size) {
    const int*   ps  = (const int*)d_in[0];
    const float* emb = (const float*)d_in[1];
    const float* cw  = (const float*)d_in[2];
    const float* cb  = (const float*)d_in[3];
    const float* wp  = (const float*)d_in[4];
    const float* bpv = (const float*)d_in[5];
    const float* wg  = (const float*)d_in[6];
    const float* bgv = (const float*)d_in[7];
    float* out = (float*)d_out;

    precomputeP<<<EWORD / 2, 512>>>(emb, cw);

    const int smem2 = VOCAB * KW * 32 * 4 + 64 * SY_STRIDE * 4;
    cudaFuncSetAttribute(conv_max_kernel,
                         cudaFuncAttributeMaxDynamicSharedMemorySize, smem2);
    conv_max_kernel<<<dim3(128, 5), 512, smem2>>>(ps, cb, wp, wg);

    cudaFuncSetAttribute(highway_mma,
                         cudaFuncAttributeMaxDynamicSharedMemorySize, SM3_B);
    highway_mma<<<dim3(NWORDS / 128, 8), 256, SM3_B>>>(bpv, bgv, out);
}

// round 13
// speedup vs baseline: 1.1174x; 1.1174x over previous
#include <cuda_runtime.h>
#include <cuda_bf16.h>
#include <cuda_fp16.h>
#include <math.h>
#include <stdint.h>

// Problem constants
#define B_      128
#define S_      256
#define MW      21
#define VOCAB   100
#define ECHAR   50
#define EWORD   256
#define KW      5
#define T_OUT   17
#define NWORDS  (B_ * S_)       // 32768

// Scratch
__device__ float   g_P [VOCAB * KW * EWORD];   // fp32 P (kept for reference)
__device__ __half2 g_Pf[4 * VOCAB * KW * 32];  // fp16 P, conv layout [eb][v][k][ep]
__device__ float   g_Y [NWORDS * EWORD];       // fp32 (exact passthrough)
__device__ __half  g_Yf[NWORDS * EWORD];       // fp16 Y (GEMM A operand)
// Interleaved weights: row r = 2*n + pg (pg: 0=proj, 1=gate), [r][k], fp16
__device__ __half  g_Wf[512 * EWORD];

typedef unsigned long long ull;

__device__ __forceinline__ uint32_t smem_u32(const void* p) {
    uint32_t a;
    asm("{ .reg .u64 t; cvta.to.shared.u64 t, %1; cvt.u32.u64 %0, t; }"
        : "=r"(a) : "l"(p));
    return a;
}

// ---- warp-level mma + cp.async (sm_80 baseline PTX) ----
#define LDSM4(r, addr) \
    asm volatile("ldmatrix.sync.aligned.m8n8.x4.shared.b16 {%0,%1,%2,%3}, [%4];" \
        : "=r"((r)[0]), "=r"((r)[1]), "=r"((r)[2]), "=r"((r)[3]) : "r"(addr))

#define MMA_F16(d, a, b0, b1) \
    asm volatile("mma.sync.aligned.m16n8k16.row.col.f32.f16.f16.f32 " \
        "{%0,%1,%2,%3}, {%4,%5,%6,%7}, {%8,%9}, {%0,%1,%2,%3};" \
        : "+f"((d)[0]), "+f"((d)[1]), "+f"((d)[2]), "+f"((d)[3]) \
        : "r"((a)[0]), "r"((a)[1]), "r"((a)[2]), "r"((a)[3]), \
          "r"(b0), "r"(b1))

#define CP16(dst, src) \
    asm volatile("cp.async.cg.shared.global [%0], [%1], 16;" \
                 :: "r"(dst), "l"(src) : "memory")
#define CP_COMMIT() asm volatile("cp.async.commit_group;" ::: "memory")
#define CP_WAIT2()  asm volatile("cp.async.wait_group 2;" ::: "memory")
#define CP_WAIT1()  asm volatile("cp.async.wait_group 1;" ::: "memory")
#define CP_WAIT0()  asm volatile("cp.async.wait_group 0;" ::: "memory")

// ---------------------------------------------------------------------------
// Kernel 1: blocks 0..127: P[v,k,e] for e pair (fp32 + fp16 conv layout).
//           blocks 128..191: W fp16 convert (rides the idle SMs).
// ---------------------------------------------------------------------------
__global__ void __launch_bounds__(512)
precomputeP(const float* __restrict__ emb, const float* __restrict__ cw,
            const float* __restrict__ Wp, const float* __restrict__ Wg) {
    const int tid = threadIdx.x;

    if (blockIdx.x >= 128) {            // W convert plane
        const int gid = (blockIdx.x - 128) * 512 + tid;
#pragma unroll
        for (int i = gid; i < 65536; i += 32768) {
            const int n = i >> 8, k = i & 255;
            g_Wf[(2 * n + 0) * EWORD + k] = __float2half_rn(Wp[i]);
            g_Wf[(2 * n + 1) * EWORD + k] = __float2half_rn(Wg[i]);
        }
        return;
    }

    __shared__ float s_emb[VOCAB * ECHAR];
    __shared__ float s_cw[2 * ECHAR * KW];
    const int e0 = blockIdx.x * 2;

    for (int i = tid; i < VOCAB * ECHAR; i += 512) s_emb[i] = emb[i];
    if (tid < 2 * ECHAR * KW)
        s_cw[tid] = cw[e0 * (ECHAR * KW) + tid];
    __syncthreads();

    // 500 (v,k) items; each thread computes both e's of the pair
    if (tid < VOCAB * KW) {
        const int v = tid / KW;
        const int k = tid - v * KW;
        float a0 = 0.f, a1 = 0.f;
#pragma unroll 10
        for (int c = 0; c < ECHAR; c++) {
            const float ev = s_emb[v * ECHAR + c];
            a0 += s_cw[0 * (ECHAR * KW) + c * KW + k] * ev;
            a1 += s_cw[1 * (ECHAR * KW) + c * KW + k] * ev;
        }
        g_P[v * (KW * EWORD) + k * EWORD + e0 + 0] = a0;
        g_P[v * (KW * EWORD) + k * EWORD + e0 + 1] = a1;
        const int eb = e0 >> 6;
        const int ep = (e0 & 63) >> 1;
        g_Pf[eb * (VOCAB * KW * 32) + v * 160 + k * 32 + ep] =
            __floats2half2_rn(a0, a1);
    }
}

// ---------------------------------------------------------------------------
// Kernel 2: conv-as-table-lookup + ReLU + maxpool — fully fp16 inner loop.
// P slice staged via cp.async straight copy from g_Pf. grid (128, 4).
// ---------------------------------------------------------------------------
#define SY_STRIDE 257

__global__ void __launch_bounds__(512)
conv_max_kernel(const int* __restrict__ ps, const float* __restrict__ cb) {
    const int tid = threadIdx.x;

    extern __shared__ char smraw[];
    __half2* sPh = (__half2*)smraw;                       // 16000 half2
    float*   sY  = (float*)(smraw + VOCAB * KW * 32 * 4);
    const uint32_t sPb = smem_u32(smraw);

    const int e0 = blockIdx.y * 64;
    const int w0 = blockIdx.x * 256;

    // stage P slice: 64000 B = 4000 x 16B cp.async lines
    {
        const char* src = (const char*)(g_Pf + blockIdx.y * (VOCAB * KW * 32));
#pragma unroll
        for (int q = 0; q < 8; q++) {
            const int i = tid + q * 512;
            if (i < 4000) CP16(sPb + i * 16, src + i * 16);
        }
        CP_COMMIT();
    }
    CP_WAIT0();
    __syncthreads();

    const int el2 = tid & 31;
    const int wl  = tid >> 5;
    const float2 bias = *(const float2*)&cb[e0 + el2 * 2];

    for (int it = 0; it < 16; it++) {
        const int wloc = it * 16 + wl;
        const int* cid = ps + (w0 + wloc) * MW;

        int off[MW];
#pragma unroll
        for (int j = 0; j < MW; j++)
            off[j] = __ldg(&cid[j]) * (KW * 32) + el2;

        __half2 mh = __float2half2_rn(-60000.f);
#pragma unroll
        for (int t = 0; t < T_OUT; t++) {
            const __half2 u0 = sPh[off[t + 0] + 0 * 32];
            const __half2 u1 = sPh[off[t + 1] + 1 * 32];
            const __half2 u2 = sPh[off[t + 2] + 2 * 32];
            const __half2 u3 = sPh[off[t + 3] + 3 * 32];
            const __half2 u4 = sPh[off[t + 4] + 4 * 32];
            const __half2 s = __hadd2(__hadd2(__hadd2(u0, u1),
                                              __hadd2(u2, u3)), u4);
            mh = __hmax2(mh, s);
        }
        const float2 f = __half22float2(mh);
        sY[(el2 * 2 + 0) * SY_STRIDE + wloc] = fmaxf(f.x + bias.x, 0.f);
        sY[(el2 * 2 + 1) * SY_STRIDE + wloc] = fmaxf(f.y + bias.y, 0.f);
    }
    __syncthreads();

    for (int i = tid; i < 64 * 256; i += 512) {
        const int w = i >> 6, e = i & 63;
        const float y = sY[e * SY_STRIDE + w];
        const int gi = (w0 + w) * EWORD + e0 + e;
        g_Y[gi]  = y;
        g_Yf[gi] = __float2half_rn(y);
    }
}

// ---------------------------------------------------------------------------
// Kernel 3: highway dual-GEMM (R11 config): single-term fp16, K-chunks of
// 64, 3-stage cp.async pipeline, 2 CTAs/SM, SMEM-staged coalesced epilogue.
// CTA 256 thr (8 warps: 2m x 4n), tile 128m x 128 interleaved rows (64 n).
// grid (256, 4).
// ---------------------------------------------------------------------------
#define RSTR    144
#define OFF_A   0
#define OFF_B   18432
#define STAGE_B 36864
#define SM3_B   (3 * STAGE_B)           // 110592
#define EPI_STR 68

static __device__ __forceinline__ void stage_chunk(uint32_t sb, int tid,
                                                   int m0, int rb, int kb) {
#pragma unroll
    for (int q = 0; q < 4; q++) {
        const int idx = tid + q * 256;
        const int r = idx >> 3, c = idx & 7;
        const uint32_t so = r * RSTR + c * 16;
        CP16(sb + OFF_A + so,
             (const char*)g_Yf + ((long)(m0 + r) * EWORD + kb + c * 8) * 2);
        CP16(sb + OFF_B + so,
             (const char*)g_Wf + ((long)(rb + r) * EWORD + kb + c * 8) * 2);
    }
    CP_COMMIT();
}

__global__ void __launch_bounds__(256, 2)
highway_mma(const float* __restrict__ bp, const float* __restrict__ bg,
            float* __restrict__ out) {
    extern __shared__ char sm[];
    const uint32_t smb = smem_u32(sm);

    const int tid = threadIdx.x;
    const int wid = tid >> 5;
    const int lane = tid & 31;
    const int wm = wid & 1;
    const int wn = wid >> 1;
    const int m0 = blockIdx.x * 128;
    const int rb = blockIdx.y * 128;

    float acc[4][4][4];
#pragma unroll
    for (int i = 0; i < 4; i++)
#pragma unroll
        for (int j = 0; j < 4; j++)
#pragma unroll
            for (int c = 0; c < 4; c++) acc[i][j][c] = 0.f;

    const int laneRow = lane & 15;
    const int laneHi  = (lane >> 4) * 16;

    stage_chunk(smb + 0 * STAGE_B, tid, m0, rb, 0);
    stage_chunk(smb + 1 * STAGE_B, tid, m0, rb, 64);
    stage_chunk(smb + 2 * STAGE_B, tid, m0, rb, 128);

#pragma unroll
    for (int ch = 0; ch < 4; ch++) {
        if (ch <= 1) CP_WAIT2();
        else if (ch == 2) CP_WAIT1();
        else CP_WAIT0();
        __syncthreads();
        const uint32_t st = smb + (uint32_t)(ch % 3) * STAGE_B;

#pragma unroll
        for (int ks = 0; ks < 4; ks++) {
            const uint32_t kboff = ks * 32 + laneHi;

            uint32_t af[4][4];
#pragma unroll
            for (int mt = 0; mt < 4; mt++)
                LDSM4(af[mt], st + OFF_A
                      + (wm * 64 + mt * 16 + laneRow) * RSTR + kboff);

            uint32_t b0[4], b1[4];
#pragma unroll
            for (int tp = 0; tp < 2; tp++) {
                uint32_t q[4];
                LDSM4(q, st + OFF_B
                      + (wn * 32 + tp * 16 + laneRow) * RSTR + kboff);
                b0[2*tp] = q[0]; b0[2*tp+1] = q[1];
                b1[2*tp] = q[2]; b1[2*tp+1] = q[3];
            }

#pragma unroll
            for (int mt = 0; mt < 4; mt++)
#pragma unroll
                for (int j = 0; j < 4; j++)
                    MMA_F16(acc[mt][j], af[mt], b0[j], b1[j]);
        }

        __syncthreads();
        if (ch + 3 < 4)
            stage_chunk(smb + (uint32_t)(ch % 3) * STAGE_B, tid, m0, rb,
                        (ch + 3) * 64);
    }

    // ---- Epilogue phase 1: (p, g) to conflict-free padded SMEM tiles ----
    float* sPf = (float*)sm;
    float* sGf = sPf + 128 * EPI_STR;
    const int nb  = rb >> 1;
    const int nl0 = wn * 16 + (lane & 3);

#pragma unroll
    for (int mt = 0; mt < 4; mt++) {
        const int ml = wm * 64 + mt * 16 + (lane >> 2);
#pragma unroll
        for (int j = 0; j < 4; j++) {
            const int nl = nl0 + j * 4;
            const float bpn = __ldg(&bp[nb + nl]);
            const float bgn = __ldg(&bg[nb + nl]);
            sPf[ml * EPI_STR + nl] = fmaxf(acc[mt][j][0] + bpn, 0.f);
            sGf[ml * EPI_STR + nl] =
                1.f / (1.f + __expf(-(acc[mt][j][1] + bgn)));
            sPf[(ml + 8) * EPI_STR + nl] = fmaxf(acc[mt][j][2] + bpn, 0.f);
            sGf[(ml + 8) * EPI_STR + nl] =
                1.f / (1.f + __expf(-(acc[mt][j][3] + bgn)));
        }
    }
    __syncthreads();

    // ---- Epilogue phase 2: fully coalesced float4 pass ----
#pragma unroll
    for (int q = 0; q < 8; q++) {
        const int i  = tid + q * 256;
        const int ml = i >> 4;
        const int c4 = (i & 15) << 2;
        const int gi = (m0 + ml) * EWORD + nb + c4;
        const float4 y4 = *(const float4*)&g_Y[gi];
        const float4 p4 = *(const float4*)&sPf[ml * EPI_STR + c4];
        const float4 g4 = *(const float4*)&sGf[ml * EPI_STR + c4];
        float4 o;
        o.x = g4.x * p4.x + (1.f - g4.x) * y4.x;
        o.y = g4.y * p4.y + (1.f - g4.y) * y4.y;
        o.z = g4.z * p4.z + (1.f - g4.z) * y4.z;
        o.w = g4.w * p4.w + (1.f - g4.w) * y4.w;
        *(float4*)&out[gi] = o;
    }
}

// ---------------------------------------------------------------------------
extern "C" void kernel_launch(void* const* d_in, const int* in_sizes, int n_in,
                              void* d_out, int out_size) {
    const int*   ps  = (const int*)d_in[0];
    const float* emb = (const float*)d_in[1];
    const float* cw  = (const float*)d_in[2];
    const float* cb  = (const float*)d_in[3];
    const float* wp  = (const float*)d_in[4];
    const float* bpv = (const float*)d_in[5];
    const float* wg  = (const float*)d_in[6];
    const float* bgv = (const float*)d_in[7];
    float* out = (float*)d_out;

    precomputeP<<<192, 512>>>(emb, cw, wp, wg);

    const int smem2 = VOCAB * KW * 32 * 4 + 64 * SY_STRIDE * 4;
    cudaFuncSetAttribute(conv_max_kernel,
                         cudaFuncAttributeMaxDynamicSharedMemorySize, smem2);
    conv_max_kernel<<<dim3(128, 4), 512, smem2>>>(ps, cb);

    cudaFuncSetAttribute(highway_mma,
                         cudaFuncAttributeMaxDynamicSharedMemorySize, SM3_B);
    highway_mma<<<dim3(NWORDS / 128, 4), 256, SM3_B>>>(bpv, bgv, out);
}

// round 15
// speedup vs baseline: 1.1933x; 1.0679x over previous
#include <cuda_runtime.h>
#include <cuda_fp16.h>
#include <math.h>
#include <stdint.h>

// Problem constants
#define B_      128
#define S_      256
#define MW      21
#define VOCAB   100
#define ECHAR   50
#define EWORD   256
#define KW      5
#define T_OUT   17
#define NWORDS  (B_ * S_)       // 32768

// Scratch (only the two small precomputed tables — Y never hits DRAM)
__device__ __half2 g_Pf[4 * VOCAB * KW * 32];  // fp16 P, conv layout [eb][v][k][ep]
__device__ __half  g_Wf[512 * EWORD];          // interleaved W rows r=2n+pg, [r][k]

__device__ __forceinline__ uint32_t smem_u32(const void* p) {
    uint32_t a;
    asm("{ .reg .u64 t; cvta.to.shared.u64 t, %1; cvt.u32.u64 %0, t; }"
        : "=r"(a) : "l"(p));
    return a;
}

#define LDSM4(r, addr) \
    asm volatile("ldmatrix.sync.aligned.m8n8.x4.shared.b16 {%0,%1,%2,%3}, [%4];" \
        : "=r"((r)[0]), "=r"((r)[1]), "=r"((r)[2]), "=r"((r)[3]) : "r"(addr))

#define MMA_F16(d, a, b0, b1) \
    asm volatile("mma.sync.aligned.m16n8k16.row.col.f32.f16.f16.f32 " \
        "{%0,%1,%2,%3}, {%4,%5,%6,%7}, {%8,%9}, {%0,%1,%2,%3};" \
        : "+f"((d)[0]), "+f"((d)[1]), "+f"((d)[2]), "+f"((d)[3]) \
        : "r"((a)[0]), "r"((a)[1]), "r"((a)[2]), "r"((a)[3]), \
          "r"(b0), "r"(b1))

#define CP16(dst, src) \
    asm volatile("cp.async.cg.shared.global [%0], [%1], 16;" \
                 :: "r"(dst), "l"(src) : "memory")
#define CP_COMMIT() asm volatile("cp.async.commit_group;" ::: "memory")
#define CP_WAIT2()  asm volatile("cp.async.wait_group 2;" ::: "memory")
#define CP_WAIT1()  asm volatile("cp.async.wait_group 1;" ::: "memory")
#define CP_WAIT0()  asm volatile("cp.async.wait_group 0;" ::: "memory")

// ---------------------------------------------------------------------------
// Kernel 1: blocks 0..127: P[v,k,e] fp16 table; blocks 128..191: W fp16.
// ---------------------------------------------------------------------------
__global__ void __launch_bounds__(512)
precomputeP(const float* __restrict__ emb, const float* __restrict__ cw,
            const float* __restrict__ Wp, const float* __restrict__ Wg) {
    const int tid = threadIdx.x;

    if (blockIdx.x >= 128) {            // W convert plane
        const int gid = (blockIdx.x - 128) * 512 + tid;
#pragma unroll
        for (int i = gid; i < 65536; i += 32768) {
            const int n = i >> 8, k = i & 255;
            g_Wf[(2 * n + 0) * EWORD + k] = __float2half_rn(Wp[i]);
            g_Wf[(2 * n + 1) * EWORD + k] = __float2half_rn(Wg[i]);
        }
        return;
    }

    __shared__ float s_emb[VOCAB * ECHAR];
    __shared__ float s_cw[2 * ECHAR * KW];
    const int e0 = blockIdx.x * 2;

    for (int i = tid; i < VOCAB * ECHAR; i += 512) s_emb[i] = emb[i];
    if (tid < 2 * ECHAR * KW)
        s_cw[tid] = cw[e0 * (ECHAR * KW) + tid];
    __syncthreads();

    if (tid < VOCAB * KW) {
        const int v = tid / KW;
        const int k = tid - v * KW;
        float a0 = 0.f, a1 = 0.f;
#pragma unroll 10
        for (int c = 0; c < ECHAR; c++) {
            const float ev = s_emb[v * ECHAR + c];
            a0 += s_cw[0 * (ECHAR * KW) + c * KW + k] * ev;
            a1 += s_cw[1 * (ECHAR * KW) + c * KW + k] * ev;
        }
        const int eb = e0 >> 6;
        const int ep = (e0 & 63) >> 1;
        g_Pf[eb * (VOCAB * KW * 32) + v * 160 + k * 32 + ep] =
            __floats2half2_rn(a0, a1);
    }
}

// ---------------------------------------------------------------------------
// Kernel 2 (FUSED): conv + maxpool + highway dual-GEMM. CTA = 256 words,
// 512 thr, grid 128 (1 wave). Y lives in SMEM (Ys[256 words][528 B]) between
// phases — zero DRAM round-trip. Row = 256 fp16 + 16B pad (33x16B, odd).
// ---------------------------------------------------------------------------
#define YS_STR   528                    // bytes per Ys row
#define YS_H2    132                    // half2 elements per Ys row (528/4)
#define WORK     135168                 // 256 * 528
#define RSTR     144                    // B-stage row stride
#define BSTAGE   18432                  // 128 rows * 144
#define EPI_N    68                     // epilogue float stride
#define PG_HALF  34816                  // 128*68*4
#define SM_TOTAL (WORK + 69632)         // 204800

__global__ void __launch_bounds__(512, 1)
fused_kernel(const int* __restrict__ ps, const float* __restrict__ cb,
             const float* __restrict__ bp, const float* __restrict__ bg,
             float* __restrict__ out) {
    extern __shared__ char sm[];
    const uint32_t smb = smem_u32(sm);
    const uint32_t wkb = smb + WORK;

    const int tid  = threadIdx.x;
    const int lane = tid & 31;
    const int wid  = tid >> 5;
    const int w0   = blockIdx.x * 256;

    __half2* sYs2 = (__half2*)sm;              // [word][YS_H2] half2
    __half2* sPh  = (__half2*)(sm + WORK);     // conv P slice

    // ================= Phase 1: conv + maxpool into Ys =================
    {
        const int el2 = tid & 31;
        const int wl  = tid >> 5;
        for (int es = 0; es < 4; es++) {
            __syncthreads();       // previous slice's sPh readers done
            const char* src = (const char*)(g_Pf + es * (VOCAB * KW * 32));
#pragma unroll
            for (int q = 0; q < 8; q++) {
                const int i = tid + q * 512;
                if (i < 4000) CP16(wkb + i * 16, src + i * 16);
            }
            CP_COMMIT();
            CP_WAIT0();
            __syncthreads();

            const float2 bias = *(const float2*)&cb[es * 64 + el2 * 2];

            for (int it = 0; it < 16; it++) {
                const int wloc = it * 16 + wl;
                const int* cid = ps + (w0 + wloc) * MW;

                int off[MW];
#pragma unroll
                for (int j = 0; j < MW; j++)
                    off[j] = __ldg(&cid[j]) * (KW * 32) + el2;

                __half2 mh = __float2half2_rn(-60000.f);
#pragma unroll
                for (int t = 0; t < T_OUT; t++) {
                    const __half2 u0 = sPh[off[t + 0] + 0 * 32];
                    const __half2 u1 = sPh[off[t + 1] + 1 * 32];
                    const __half2 u2 = sPh[off[t + 2] + 2 * 32];
                    const __half2 u3 = sPh[off[t + 3] + 3 * 32];
                    const __half2 u4 = sPh[off[t + 4] + 4 * 32];
                    const __half2 s = __hadd2(__hadd2(__hadd2(u0, u1),
                                                      __hadd2(u2, u3)), u4);
                    mh = __hmax2(mh, s);
                }
                const float2 f = __half22float2(mh);
                const float y0 = fmaxf(f.x + bias.x, 0.f);
                const float y1 = fmaxf(f.y + bias.y, 0.f);
                sYs2[wloc * YS_H2 + es * 32 + el2] = __floats2half2_rn(y0, y1);
            }
        }
    }
    __syncthreads();    // Ys complete

    // ================= Phase 2: dual GEMM + highway epilogue =============
    const int wm = wid & 3;          // 64m each (256 m total)
    const int wn = wid >> 2;         // 32 interleaved rows each (64 per pass)
    const int laneRow = lane & 15;
    const int laneHi  = (lane >> 4) * 16;

    float* sPf = (float*)(sm + WORK);
    float* sGf = (float*)(sm + WORK + PG_HALF);

    for (int nr = 0; nr < 4; nr++) {
        const int rb = nr * 128;     // interleaved-row base
        const int nb = nr * 64;      // n base

        // B prologue: 3 k-chunks of 64 (1024 16B lines each -> 2/thread)
#pragma unroll
        for (int st = 0; st < 3; st++) {
            const uint32_t sb = wkb + st * BSTAGE;
#pragma unroll
            for (int q = 0; q < 2; q++) {
                const int idx = tid + q * 512;
                const int r = idx >> 3, c = idx & 7;
                CP16(sb + r * RSTR + c * 16,
                     (const char*)g_Wf
                     + ((long)(rb + r) * EWORD + st * 64 + c * 8) * 2);
            }
            CP_COMMIT();
        }

        float acc[4][4][4];
#pragma unroll
        for (int i = 0; i < 4; i++)
#pragma unroll
            for (int j = 0; j < 4; j++)
#pragma unroll
                for (int c = 0; c < 4; c++) acc[i][j][c] = 0.f;

#pragma unroll
        for (int ch = 0; ch < 4; ch++) {
            if (ch <= 1) CP_WAIT2();
            else if (ch == 2) CP_WAIT1();
            else CP_WAIT0();
            __syncthreads();
            const uint32_t st = wkb + (uint32_t)(ch % 3) * BSTAGE;

#pragma unroll
            for (int ks = 0; ks < 4; ks++) {
                const uint32_t kA = ch * 128 + ks * 32 + laneHi;
                const uint32_t kB = ks * 32 + laneHi;

                uint32_t af[4][4];
#pragma unroll
                for (int mt = 0; mt < 4; mt++)
                    LDSM4(af[mt], smb
                          + (wm * 64 + mt * 16 + laneRow) * YS_STR + kA);

                uint32_t b0[4], b1[4];
#pragma unroll
                for (int tp = 0; tp < 2; tp++) {
                    uint32_t q[4];
                    LDSM4(q, st + (wn * 32 + tp * 16 + laneRow) * RSTR + kB);
                    b0[2*tp] = q[0]; b0[2*tp+1] = q[1];
                    b1[2*tp] = q[2]; b1[2*tp+1] = q[3];
                }

#pragma unroll
                for (int mt = 0; mt < 4; mt++)
#pragma unroll
                    for (int j = 0; j < 4; j++)
                        MMA_F16(acc[mt][j], af[mt], b0[j], b1[j]);
            }

            __syncthreads();
            if (ch == 0) {       // stage kb=192 into buffer 0
                const uint32_t sb = wkb;
#pragma unroll
                for (int q = 0; q < 2; q++) {
                    const int idx = tid + q * 512;
                    const int r = idx >> 3, c = idx & 7;
                    CP16(sb + r * RSTR + c * 16,
                         (const char*)g_Wf
                         + ((long)(rb + r) * EWORD + 192 + c * 8) * 2);
                }
                CP_COMMIT();
            }
        }

        // ---- epilogue: two m-batches of 128 through staged SMEM ----
        const int nl0 = wn * 16 + (lane & 3);
#pragma unroll
        for (int b = 0; b < 2; b++) {
            if ((wm >> 1) == b) {
                const int wmL = wm & 1;      // 0..1 within batch
#pragma unroll
                for (int mt = 0; mt < 4; mt++) {
                    const int ml = wmL * 64 + mt * 16 + (lane >> 2);
#pragma unroll
                    for (int j = 0; j < 4; j++) {
                        const int nl = nl0 + j * 4;
                        const float bpn = __ldg(&bp[nb + nl]);
                        const float bgn = __ldg(&bg[nb + nl]);
                        sPf[ml * EPI_N + nl] = fmaxf(acc[mt][j][0] + bpn, 0.f);
                        sGf[ml * EPI_N + nl] =
                            1.f / (1.f + __expf(-(acc[mt][j][1] + bgn)));
                        sPf[(ml + 8) * EPI_N + nl] =
                            fmaxf(acc[mt][j][2] + bpn, 0.f);
                        sGf[(ml + 8) * EPI_N + nl] =
                            1.f / (1.f + __expf(-(acc[mt][j][3] + bgn)));
                    }
                }
            }
            __syncthreads();

            // coalesced pass: 128m x 64n, y from Ys fp16
#pragma unroll
            for (int q = 0; q < 4; q++) {
                const int i  = tid + q * 512;     // 0..2047
                const int ml = i >> 4;
                const int c4 = (i & 15) << 2;
                const int m  = b * 128 + ml;
                const uint2 yraw = *(const uint2*)
                    ((const char*)sm + m * YS_STR + (nb + c4) * 2);
                const float2 ylo = __half22float2(*(const __half2*)&yraw.x);
                const float2 yhi = __half22float2(*(const __half2*)&yraw.y);
                const float4 p4 = *(const float4*)&sPf[ml * EPI_N + c4];
                const float4 g4 = *(const float4*)&sGf[ml * EPI_N + c4];
                float4 o;
                o.x = g4.x * p4.x + (1.f - g4.x) * ylo.x;
                o.y = g4.y * p4.y + (1.f - g4.y) * ylo.y;
                o.z = g4.z * p4.z + (1.f - g4.z) * yhi.x;
                o.w = g4.w * p4.w + (1.f - g4.w) * yhi.y;
                *(float4*)&out[(w0 + m) * EWORD + nb + c4] = o;
            }
            __syncthreads();
        }
    }
}

// ---------------------------------------------------------------------------
extern "C" void kernel_launch(void* const* d_in, const int* in_sizes, int n_in,
                              void* d_out, int out_size) {
    const int*   ps  = (const int*)d_in[0];
    const float* emb = (const float*)d_in[1];
    const float* cw  = (const float*)d_in[2];
    const float* cb  = (const float*)d_in[3];
    const float* wp  = (const float*)d_in[4];
    const float* bpv = (const float*)d_in[5];
    const float* wg  = (const float*)d_in[6];
    const float* bgv = (const float*)d_in[7];
    float* out = (float*)d_out;

    precomputeP<<<192, 512>>>(emb, cw, wp, wg);

    cudaFuncSetAttribute(fused_kernel,
                         cudaFuncAttributeMaxDynamicSharedMemorySize, SM_TOTAL);
    fused_kernel<<<NWORDS / 256, 512, SM_TOTAL>>>(ps, cb, bpv, bgv, out);
}

// round 16
// speedup vs baseline: 1.2424x; 1.0412x over previous
#include <cuda_runtime.h>
#include <cuda_fp16.h>
#include <math.h>
#include <stdint.h>

// Problem constants
#define B_      128
#define S_      256
#define MW      21
#define VOCAB   100
#define ECHAR   50
#define EWORD   256
#define KW      5
#define T_OUT   17
#define NWORDS  (B_ * S_)       // 32768

// Scratch (only the two small precomputed tables — Y never hits DRAM)
__device__ __half2 g_Pf[4 * VOCAB * KW * 32];  // fp16 P, conv layout [eb][v][k][ep]
__device__ __half  g_Wf[512 * EWORD];          // interleaved W rows r=2n+pg, [r][k]

__device__ __forceinline__ uint32_t smem_u32(const void* p) {
    uint32_t a;
    asm("{ .reg .u64 t; cvta.to.shared.u64 t, %1; cvt.u32.u64 %0, t; }"
        : "=r"(a) : "l"(p));
    return a;
}

#define LDSM4(r, addr) \
    asm volatile("ldmatrix.sync.aligned.m8n8.x4.shared.b16 {%0,%1,%2,%3}, [%4];" \
        : "=r"((r)[0]), "=r"((r)[1]), "=r"((r)[2]), "=r"((r)[3]) : "r"(addr))

#define MMA_F16(d, a, b0, b1) \
    asm volatile("mma.sync.aligned.m16n8k16.row.col.f32.f16.f16.f32 " \
        "{%0,%1,%2,%3}, {%4,%5,%6,%7}, {%8,%9}, {%0,%1,%2,%3};" \
        : "+f"((d)[0]), "+f"((d)[1]), "+f"((d)[2]), "+f"((d)[3]) \
        : "r"((a)[0]), "r"((a)[1]), "r"((a)[2]), "r"((a)[3]), \
          "r"(b0), "r"(b1))

#define CP16(dst, src) \
    asm volatile("cp.async.cg.shared.global [%0], [%1], 16;" \
                 :: "r"(dst), "l"(src) : "memory")
#define CP_COMMIT() asm volatile("cp.async.commit_group;" ::: "memory")
#define CP_WAIT2()  asm volatile("cp.async.wait_group 2;" ::: "memory")
#define CP_WAIT1()  asm volatile("cp.async.wait_group 1;" ::: "memory")
#define CP_WAIT0()  asm volatile("cp.async.wait_group 0;" ::: "memory")

// ---------------------------------------------------------------------------
// Kernel 1: blocks 0..127: P[v,k,e] fp16 table; blocks 128..191: W fp16.
// ---------------------------------------------------------------------------
__global__ void __launch_bounds__(512)
precomputeP(const float* __restrict__ emb, const float* __restrict__ cw,
            const float* __restrict__ Wp, const float* __restrict__ Wg) {
    const int tid = threadIdx.x;

    if (blockIdx.x >= 128) {            // W convert plane
        const int gid = (blockIdx.x - 128) * 512 + tid;
#pragma unroll
        for (int i = gid; i < 65536; i += 32768) {
            const int n = i >> 8, k = i & 255;
            g_Wf[(2 * n + 0) * EWORD + k] = __float2half_rn(Wp[i]);
            g_Wf[(2 * n + 1) * EWORD + k] = __float2half_rn(Wg[i]);
        }
        return;
    }

    __shared__ float s_emb[VOCAB * ECHAR];
    __shared__ float s_cw[2 * ECHAR * KW];
    const int e0 = blockIdx.x * 2;

    for (int i = tid; i < VOCAB * ECHAR; i += 512) s_emb[i] = emb[i];
    if (tid < 2 * ECHAR * KW)
        s_cw[tid] = cw[e0 * (ECHAR * KW) + tid];
    __syncthreads();

    if (tid < VOCAB * KW) {
        const int v = tid / KW;
        const int k = tid - v * KW;
        float a0 = 0.f, a1 = 0.f;
#pragma unroll 10
        for (int c = 0; c < ECHAR; c++) {
            const float ev = s_emb[v * ECHAR + c];
            a0 += s_cw[0 * (ECHAR * KW) + c * KW + k] * ev;
            a1 += s_cw[1 * (ECHAR * KW) + c * KW + k] * ev;
        }
        const int eb = e0 >> 6;
        const int ep = (e0 & 63) >> 1;
        g_Pf[eb * (VOCAB * KW * 32) + v * 160 + k * 32 + ep] =
            __floats2half2_rn(a0, a1);
    }
}

// ---------------------------------------------------------------------------
// Kernel 2 (FUSED): conv + maxpool + highway dual-GEMM.
// 1024 threads (8 warps/SMSP for latency hiding), CTA = 256 words, grid 128.
// Y lives in SMEM (Ys[256 words][528 B]) between phases.
// ---------------------------------------------------------------------------
#define YS_STR   528                    // bytes per Ys row
#define YS_H2    132                    // half2 elements per Ys row
#define WORK     135168                 // 256 * 528
#define RSTR     144                    // B-stage row stride
#define BSTAGE   18432                  // 128 rows * 144
#define EPI_N    68                     // epilogue float stride
#define PG_HALF  34816                  // 128*68*4
#define SM_TOTAL (WORK + 69632)         // 204800
#define NT       1024

__global__ void __launch_bounds__(NT, 1)
fused_kernel(const int* __restrict__ ps, const float* __restrict__ cb,
             const float* __restrict__ bp, const float* __restrict__ bg,
             float* __restrict__ out) {
    extern __shared__ char sm[];
    const uint32_t smb = smem_u32(sm);
    const uint32_t wkb = smb + WORK;

    const int tid  = threadIdx.x;
    const int lane = tid & 31;
    const int wid  = tid >> 5;           // 0..31
    const int w0   = blockIdx.x * 256;

    __half2* sYs2 = (__half2*)sm;              // [word][YS_H2] half2
    __half2* sPh  = (__half2*)(sm + WORK);     // conv P slice

    // ================= Phase 1: conv + maxpool into Ys =================
    {
        const int el2 = tid & 31;
        const int wl  = wid;                   // 32 words in flight
        for (int es = 0; es < 4; es++) {
            __syncthreads();
            const char* src = (const char*)(g_Pf + es * (VOCAB * KW * 32));
#pragma unroll
            for (int q = 0; q < 4; q++) {
                const int i = tid + q * NT;
                if (i < 4000) CP16(wkb + i * 16, src + i * 16);
            }
            CP_COMMIT();
            CP_WAIT0();
            __syncthreads();

            const float2 bias = *(const float2*)&cb[es * 64 + el2 * 2];

            for (int it = 0; it < 8; it++) {
                const int wloc = it * 32 + wl;
                const int* cid = ps + (w0 + wloc) * MW;

                int off[MW];
#pragma unroll
                for (int j = 0; j < MW; j++)
                    off[j] = __ldg(&cid[j]) * (KW * 32) + el2;

                __half2 mh = __float2half2_rn(-60000.f);
#pragma unroll
                for (int t = 0; t < T_OUT; t++) {
                    const __half2 u0 = sPh[off[t + 0] + 0 * 32];
                    const __half2 u1 = sPh[off[t + 1] + 1 * 32];
                    const __half2 u2 = sPh[off[t + 2] + 2 * 32];
                    const __half2 u3 = sPh[off[t + 3] + 3 * 32];
                    const __half2 u4 = sPh[off[t + 4] + 4 * 32];
                    const __half2 s = __hadd2(__hadd2(__hadd2(u0, u1),
                                                      __hadd2(u2, u3)), u4);
                    mh = __hmax2(mh, s);
                }
                const float2 f = __half22float2(mh);
                const float y0 = fmaxf(f.x + bias.x, 0.f);
                const float y1 = fmaxf(f.y + bias.y, 0.f);
                sYs2[wloc * YS_H2 + es * 32 + el2] = __floats2half2_rn(y0, y1);
            }
        }
    }
    __syncthreads();    // Ys complete

    // ================= Phase 2: dual GEMM + highway epilogue =============
    const int wm = wid & 3;          // 64m each (256 m total)
    const int wn = wid >> 2;         // 16 interleaved rows each (128 per pass)
    const int laneRow = lane & 15;
    const int laneHi  = (lane >> 4) * 16;

    float* sPf = (float*)(sm + WORK);
    float* sGf = (float*)(sm + WORK + PG_HALF);

    for (int nr = 0; nr < 4; nr++) {
        const int rb = nr * 128;     // interleaved-row base
        const int nb = nr * 64;      // n base

        // B prologue: 3 k-chunks of 64 (1024 16B lines each -> 1/thread)
#pragma unroll
        for (int st = 0; st < 3; st++) {
            const uint32_t sb = wkb + st * BSTAGE;
            const int r = tid >> 3, c = tid & 7;
            CP16(sb + r * RSTR + c * 16,
                 (const char*)g_Wf
                 + ((long)(rb + r) * EWORD + st * 64 + c * 8) * 2);
            CP_COMMIT();
        }

        float acc[4][2][4];
#pragma unroll
        for (int i = 0; i < 4; i++)
#pragma unroll
            for (int j = 0; j < 2; j++)
#pragma unroll
                for (int c = 0; c < 4; c++) acc[i][j][c] = 0.f;

#pragma unroll
        for (int ch = 0; ch < 4; ch++) {
            if (ch <= 1) CP_WAIT2();
            else if (ch == 2) CP_WAIT1();
            else CP_WAIT0();
            __syncthreads();
            const uint32_t st = wkb + (uint32_t)(ch % 3) * BSTAGE;

#pragma unroll
            for (int ks = 0; ks < 4; ks++) {
                const uint32_t kA = ch * 128 + ks * 32 + laneHi;
                const uint32_t kB = ks * 32 + laneHi;

                uint32_t q[4];
                LDSM4(q, st + (wn * 16 + laneRow) * RSTR + kB);

#pragma unroll
                for (int mt = 0; mt < 4; mt++) {
                    uint32_t af[4];
                    LDSM4(af, smb
                          + (wm * 64 + mt * 16 + laneRow) * YS_STR + kA);
                    MMA_F16(acc[mt][0], af, q[0], q[2]);
                    MMA_F16(acc[mt][1], af, q[1], q[3]);
                }
            }

            __syncthreads();
            if (ch == 0) {       // stage kb=192 into buffer 0
                const int r = tid >> 3, c = tid & 7;
                CP16(wkb + r * RSTR + c * 16,
                     (const char*)g_Wf
                     + ((long)(rb + r) * EWORD + 192 + c * 8) * 2);
                CP_COMMIT();
            }
        }

        // ---- epilogue: two m-batches of 128 through staged SMEM ----
        const int nl0 = wn * 8 + (lane & 3);
#pragma unroll
        for (int b = 0; b < 2; b++) {
            if ((wm >> 1) == b) {
                const int wmL = wm & 1;
#pragma unroll
                for (int mt = 0; mt < 4; mt++) {
                    const int ml = wmL * 64 + mt * 16 + (lane >> 2);
#pragma unroll
                    for (int j = 0; j < 2; j++) {
                        const int nl = nl0 + j * 4;
                        const float bpn = __ldg(&bp[nb + nl]);
                        const float bgn = __ldg(&bg[nb + nl]);
                        sPf[ml * EPI_N + nl] = fmaxf(acc[mt][j][0] + bpn, 0.f);
                        sGf[ml * EPI_N + nl] =
                            1.f / (1.f + __expf(-(acc[mt][j][1] + bgn)));
                        sPf[(ml + 8) * EPI_N + nl] =
                            fmaxf(acc[mt][j][2] + bpn, 0.f);
                        sGf[(ml + 8) * EPI_N + nl] =
                            1.f / (1.f + __expf(-(acc[mt][j][3] + bgn)));
                    }
                }
            }
            __syncthreads();

            // coalesced pass: 128m x 64n, y from Ys fp16
#pragma unroll
            for (int q = 0; q < 2; q++) {
                const int i  = tid + q * NT;      // 0..2047
                const int ml = i >> 4;
                const int c4 = (i & 15) << 2;
                const int m  = b * 128 + ml;
                const uint2 yraw = *(const uint2*)
                    ((const char*)sm + m * YS_STR + (nb + c4) * 2);
                const float2 ylo = __half22float2(*(const __half2*)&yraw.x);
                const float2 yhi = __half22float2(*(const __half2*)&yraw.y);
                const float4 p4 = *(const float4*)&sPf[ml * EPI_N + c4];
                const float4 g4 = *(const float4*)&sGf[ml * EPI_N + c4];
                float4 o;
                o.x = g4.x * p4.x + (1.f - g4.x) * ylo.x;
                o.y = g4.y * p4.y + (1.f - g4.y) * ylo.y;
                o.z = g4.z * p4.z + (1.f - g4.z) * yhi.x;
                o.w = g4.w * p4.w + (1.f - g4.w) * yhi.y;
                *(float4*)&out[(w0 + m) * EWORD + nb + c4] = o;
            }
            __syncthreads();
        }
    }
}

// ---------------------------------------------------------------------------
extern "C" void kernel_launch(void* const* d_in, const int* in_sizes, int n_in,
                              void* d_out, int out_size) {
    const int*   ps  = (const int*)d_in[0];
    const float* emb = (const float*)d_in[1];
    const float* cw  = (const float*)d_in[2];
    const float* cb  = (const float*)d_in[3];
    const float* wp  = (const float*)d_in[4];
    const float* bpv = (const float*)d_in[5];
    const float* wg  = (const float*)d_in[6];
    const float* bgv = (const float*)d_in[7];
    float* out = (float*)d_out;

    precomputeP<<<192, 512>>>(emb, cw, wp, wg);

    cudaFuncSetAttribute(fused_kernel,
                         cudaFuncAttributeMaxDynamicSharedMemorySize, SM_TOTAL);
    fused_kernel<<<NWORDS / 256, NT, SM_TOTAL>>>(ps, cb, bpv, bgv, out);
}

// round 17
// speedup vs baseline: 1.2760x; 1.0270x over previous
#include <cuda_runtime.h>
#include <cuda_fp16.h>
#include <math.h>
#include <stdint.h>

// Problem constants
#define B_      128
#define S_      256
#define MW      21
#define VOCAB   100
#define ECHAR   50
#define EWORD   256
#define KW      5
#define T_OUT   17
#define NWORDS  (B_ * S_)       // 32768

// Scratch (only the two small precomputed tables — Y never hits DRAM)
__device__ __half2 g_Pf[4 * VOCAB * KW * 32];  // fp16 P, conv layout [eb][v][k][ep]
__device__ __half  g_Wf[512 * EWORD];          // interleaved W rows r=2n+pg, [r][k]

__device__ __forceinline__ uint32_t smem_u32(const void* p) {
    uint32_t a;
    asm("{ .reg .u64 t; cvta.to.shared.u64 t, %1; cvt.u32.u64 %0, t; }"
        : "=r"(a) : "l"(p));
    return a;
}

#define LDSM4(r, addr) \
    asm volatile("ldmatrix.sync.aligned.m8n8.x4.shared.b16 {%0,%1,%2,%3}, [%4];" \
        : "=r"((r)[0]), "=r"((r)[1]), "=r"((r)[2]), "=r"((r)[3]) : "r"(addr))

#define MMA_F16(d, a, b0, b1) \
    asm volatile("mma.sync.aligned.m16n8k16.row.col.f32.f16.f16.f32 " \
        "{%0,%1,%2,%3}, {%4,%5,%6,%7}, {%8,%9}, {%0,%1,%2,%3};" \
        : "+f"((d)[0]), "+f"((d)[1]), "+f"((d)[2]), "+f"((d)[3]) \
        : "r"((a)[0]), "r"((a)[1]), "r"((a)[2]), "r"((a)[3]), \
          "r"(b0), "r"(b1))

#define CP16(dst, src) \
    asm volatile("cp.async.cg.shared.global [%0], [%1], 16;" \
                 :: "r"(dst), "l"(src) : "memory")
#define CP_COMMIT() asm volatile("cp.async.commit_group;" ::: "memory")
#define CP_WAIT2()  asm volatile("cp.async.wait_group 2;" ::: "memory")
#define CP_WAIT1()  asm volatile("cp.async.wait_group 1;" ::: "memory")
#define CP_WAIT0()  asm volatile("cp.async.wait_group 0;" ::: "memory")

// ---------------------------------------------------------------------------
// Kernel 1 (grid 128, one wave): P fp16 table + W fp16 convert fused.
// ---------------------------------------------------------------------------
__global__ void __launch_bounds__(512)
precomputeP(const float* __restrict__ emb, const float* __restrict__ cw,
            const float* __restrict__ Wp, const float* __restrict__ Wg) {
    const int tid = threadIdx.x;

    // W convert: 512 values per block (grid 128 x 512 = 65536)
    {
        const int i = blockIdx.x * 512 + tid;
        const int n = i >> 8, k = i & 255;
        g_Wf[(2 * n + 0) * EWORD + k] = __float2half_rn(Wp[i]);
        g_Wf[(2 * n + 1) * EWORD + k] = __float2half_rn(Wg[i]);
    }

    __shared__ float s_emb[VOCAB * ECHAR];
    __shared__ float s_cw[2 * ECHAR * KW];
    const int e0 = blockIdx.x * 2;

    for (int i = tid; i < VOCAB * ECHAR; i += 512) s_emb[i] = emb[i];
    if (tid < 2 * ECHAR * KW)
        s_cw[tid] = cw[e0 * (ECHAR * KW) + tid];
    __syncthreads();

    if (tid < VOCAB * KW) {
        const int v = tid / KW;
        const int k = tid - v * KW;
        float a0 = 0.f, a1 = 0.f;
#pragma unroll 10
        for (int c = 0; c < ECHAR; c++) {
            const float ev = s_emb[v * ECHAR + c];
            a0 += s_cw[0 * (ECHAR * KW) + c * KW + k] * ev;
            a1 += s_cw[1 * (ECHAR * KW) + c * KW + k] * ev;
        }
        const int eb = e0 >> 6;
        const int ep = (e0 & 63) >> 1;
        g_Pf[eb * (VOCAB * KW * 32) + v * 160 + k * 32 + ep] =
            __floats2half2_rn(a0, a1);
    }
}

// ---------------------------------------------------------------------------
// Kernel 2 (FUSED): conv + maxpool + highway dual-GEMM. 1024 threads,
// CTA = 256 words, grid 128. Y lives in SMEM between phases.
// GEMM warp tile: 32m x 32 interleaved rows (wm8 x wn4) — 16 LDSM-wf / 8 MMA.
// ---------------------------------------------------------------------------
#define YS_STR   528                    // bytes per Ys row
#define YS_H2    132                    // half2 elements per Ys row
#define WORK     135168                 // 256 * 528
#define RSTR     144                    // B-stage row stride
#define BSTAGE   18432                  // 128 rows * 144
#define EPI_N    68                     // epilogue float stride
#define PG_HALF  34816                  // 128*68*4
#define SM_TOTAL (WORK + 69632)         // 204800
#define NT       1024

__global__ void __launch_bounds__(NT, 1)
fused_kernel(const int* __restrict__ ps, const float* __restrict__ cb,
             const float* __restrict__ bp, const float* __restrict__ bg,
             float* __restrict__ out) {
    extern __shared__ char sm[];
    const uint32_t smb = smem_u32(sm);
    const uint32_t wkb = smb + WORK;

    const int tid  = threadIdx.x;
    const int lane = tid & 31;
    const int wid  = tid >> 5;           // 0..31
    const int w0   = blockIdx.x * 256;

    __half2* sYs2 = (__half2*)sm;              // [word][YS_H2] half2
    __half2* sPh  = (__half2*)(sm + WORK);     // conv P slice

    // ================= Phase 1: conv + maxpool into Ys =================
    {
        const int el2 = tid & 31;
        const int wl  = wid;                   // 32 words in flight
        for (int es = 0; es < 4; es++) {
            __syncthreads();
            const char* src = (const char*)(g_Pf + es * (VOCAB * KW * 32));
#pragma unroll
            for (int q = 0; q < 4; q++) {
                const int i = tid + q * NT;
                if (i < 4000) CP16(wkb + i * 16, src + i * 16);
            }
            CP_COMMIT();
            CP_WAIT0();
            __syncthreads();

            const float2 bias = *(const float2*)&cb[es * 64 + el2 * 2];

            for (int it = 0; it < 8; it++) {
                const int wloc = it * 32 + wl;
                const int* cid = ps + (w0 + wloc) * MW;

                int off[MW];
#pragma unroll
                for (int j = 0; j < MW; j++)
                    off[j] = __ldg(&cid[j]) * (KW * 32) + el2;

                __half2 mh = __float2half2_rn(-60000.f);
#pragma unroll
                for (int t = 0; t < T_OUT; t++) {
                    const __half2 u0 = sPh[off[t + 0] + 0 * 32];
                    const __half2 u1 = sPh[off[t + 1] + 1 * 32];
                    const __half2 u2 = sPh[off[t + 2] + 2 * 32];
                    const __half2 u3 = sPh[off[t + 3] + 3 * 32];
                    const __half2 u4 = sPh[off[t + 4] + 4 * 32];
                    const __half2 s = __hadd2(__hadd2(__hadd2(u0, u1),
                                                      __hadd2(u2, u3)), u4);
                    mh = __hmax2(mh, s);
                }
                const float2 f = __half22float2(mh);
                const float y0 = fmaxf(f.x + bias.x, 0.f);
                const float y1 = fmaxf(f.y + bias.y, 0.f);
                sYs2[wloc * YS_H2 + es * 32 + el2] = __floats2half2_rn(y0, y1);
            }
        }
    }
    __syncthreads();    // Ys complete

    // ================= Phase 2: dual GEMM + highway epilogue =============
    const int wm = wid & 7;          // 32m each (256 m total)
    const int wn = wid >> 3;         // 32 interleaved rows each (128 per pass)
    const int laneRow = lane & 15;
    const int laneHi  = (lane >> 4) * 16;

    float* sPf = (float*)(sm + WORK);
    float* sGf = (float*)(sm + WORK + PG_HALF);

    for (int nr = 0; nr < 4; nr++) {
        const int rb = nr * 128;     // interleaved-row base
        const int nb = nr * 64;      // n base

        // B prologue: 3 k-chunks of 64 (1024 16B lines each -> 1/thread)
#pragma unroll
        for (int st = 0; st < 3; st++) {
            const uint32_t sb = wkb + st * BSTAGE;
            const int r = tid >> 3, c = tid & 7;
            CP16(sb + r * RSTR + c * 16,
                 (const char*)g_Wf
                 + ((long)(rb + r) * EWORD + st * 64 + c * 8) * 2);
            CP_COMMIT();
        }

        float acc[2][4][4];
#pragma unroll
        for (int i = 0; i < 2; i++)
#pragma unroll
            for (int j = 0; j < 4; j++)
#pragma unroll
                for (int c = 0; c < 4; c++) acc[i][j][c] = 0.f;

#pragma unroll
        for (int ch = 0; ch < 4; ch++) {
            if (ch <= 1) CP_WAIT2();
            else if (ch == 2) CP_WAIT1();
            else CP_WAIT0();
            __syncthreads();
            const uint32_t st = wkb + (uint32_t)(ch % 3) * BSTAGE;

#pragma unroll
            for (int ks = 0; ks < 4; ks++) {
                const uint32_t kA = ch * 128 + ks * 32 + laneHi;
                const uint32_t kB = ks * 32 + laneHi;

                uint32_t b0[4], b1[4];
#pragma unroll
                for (int tp = 0; tp < 2; tp++) {
                    uint32_t q[4];
                    LDSM4(q, st + (wn * 32 + tp * 16 + laneRow) * RSTR + kB);
                    b0[2*tp]   = q[0]; b0[2*tp+1] = q[1];
                    b1[2*tp]   = q[2]; b1[2*tp+1] = q[3];
                }

#pragma unroll
                for (int mt = 0; mt < 2; mt++) {
                    uint32_t af[4];
                    LDSM4(af, smb
                          + (wm * 32 + mt * 16 + laneRow) * YS_STR + kA);
#pragma unroll
                    for (int j = 0; j < 4; j++)
                        MMA_F16(acc[mt][j], af, b0[j], b1[j]);
                }
            }

            __syncthreads();
            if (ch == 0) {       // stage kb=192 into buffer 0
                const int r = tid >> 3, c = tid & 7;
                CP16(wkb + r * RSTR + c * 16,
                     (const char*)g_Wf
                     + ((long)(rb + r) * EWORD + 192 + c * 8) * 2);
                CP_COMMIT();
            }
        }

        // ---- epilogue: two m-batches of 128 through staged SMEM ----
        const int nl0 = wn * 16 + (lane & 3);
#pragma unroll
        for (int b = 0; b < 2; b++) {
            if ((wm >> 2) == b) {
                const int wmL = wm & 3;          // 0..3 within batch
#pragma unroll
                for (int mt = 0; mt < 2; mt++) {
                    const int ml = wmL * 32 + mt * 16 + (lane >> 2);
#pragma unroll
                    for (int j = 0; j < 4; j++) {
                        const int nl = nl0 + j * 4;
                        const float bpn = __ldg(&bp[nb + nl]);
                        const float bgn = __ldg(&bg[nb + nl]);
                        sPf[ml * EPI_N + nl] = fmaxf(acc[mt][j][0] + bpn, 0.f);
                        sGf[ml * EPI_N + nl] =
                            1.f / (1.f + __expf(-(acc[mt][j][1] + bgn)));
                        sPf[(ml + 8) * EPI_N + nl] =
                            fmaxf(acc[mt][j][2] + bpn, 0.f);
                        sGf[(ml + 8) * EPI_N + nl] =
                            1.f / (1.f + __expf(-(acc[mt][j][3] + bgn)));
                    }
                }
            }
            __syncthreads();

            // coalesced pass: 128m x 64n, y from Ys fp16
#pragma unroll
            for (int q = 0; q < 2; q++) {
                const int i  = tid + q * NT;      // 0..2047
                const int ml = i >> 4;
                const int c4 = (i & 15) << 2;
                const int m  = b * 128 + ml;
                const uint2 yraw = *(const uint2*)
                    ((const char*)sm + m * YS_STR + (nb + c4) * 2);
                const float2 ylo = __half22float2(*(const __half2*)&yraw.x);
                const float2 yhi = __half22float2(*(const __half2*)&yraw.y);
                const float4 p4 = *(const float4*)&sPf[ml * EPI_N + c4];
                const float4 g4 = *(const float4*)&sGf[ml * EPI_N + c4];
                float4 o;
                o.x = g4.x * p4.x + (1.f - g4.x) * ylo.x;
                o.y = g4.y * p4.y + (1.f - g4.y) * ylo.y;
                o.z = g4.z * p4.z + (1.f - g4.z) * yhi.x;
                o.w = g4.w * p4.w + (1.f - g4.w) * yhi.y;
                *(float4*)&out[(w0 + m) * EWORD + nb + c4] = o;
            }
            __syncthreads();
        }
    }
}

// ---------------------------------------------------------------------------
extern "C" void kernel_launch(void* const* d_in, const int* in_sizes, int n_in,
                              void* d_out, int out_size) {
    const int*   ps  = (const int*)d_in[0];
    const float* emb = (const float*)d_in[1];
    const float* cw  = (const float*)d_in[2];
    const float* cb  = (const float*)d_in[3];
    const float* wp  = (const float*)d_in[4];
    const float* bpv = (const float*)d_in[5];
    const float* wg  = (const float*)d_in[6];
    const float* bgv = (const float*)d_in[7];
    float* out = (float*)d_out;

    precomputeP<<<128, 512>>>(emb, cw, wp, wg);

    cudaFuncSetAttribute(fused_kernel,
                         cudaFuncAttributeMaxDynamicSharedMemorySize, SM_TOTAL);
    fused_kernel<<<NWORDS / 256, NT, SM_TOTAL>>>(ps, cb, bpv, bgv, out);
}